// round 5
// baseline (speedup 1.0000x reference)
#include <cuda_runtime.h>

// ============================================================================
// MH2SD: attention branch is algebraically dead (softmax over size-1 axis = 1;
// attn rows sum to 1), so out = 1 + gelu(bn(grouped 3x3 conv(x4, local_w))).
//
// R4: vertical f32x2 packing. smem holds pre-packed vertical pixel pairs
// (row r, row r+1) so the inner loop is pure aligned LDS.128 + FFMA2 with
// zero input packs. 8-way split-K over ci, all-to-all smem reduction,
// distributed gelu epilogue. 66KB dyn smem -> 3 CTAs/SM, 1 wave.
// ============================================================================

#define NPD   24
#define NPIX  576
#define DIMC  128

#define VP_CI      84                  // u64 per ci: 3 vrows * 28 pairs
#define VP_BYTES   (64 * VP_CI * 8)    // 43008
#define W_CI       96                  // floats per ci: 8 och * 12
#define W_BYTES    (64 * W_CI * 4)     // 24576
#define SMEM_BYTES (VP_BYTES + W_BYTES)  // 67584

typedef unsigned long long u64;

__device__ __forceinline__ u64 pk(float lo, float hi) {
    u64 r; asm("mov.b64 %0, {%1, %2};" : "=l"(r) : "f"(lo), "f"(hi)); return r;
}
__device__ __forceinline__ void upk(float& lo, float& hi, u64 v) {
    asm("mov.b64 {%0, %1}, %2;" : "=f"(lo), "=f"(hi) : "l"(v));
}
__device__ __forceinline__ void ffma2(u64& d, u64 a, u64 b) {
    asm("fma.rn.f32x2 %0, %1, %2, %0;" : "+l"(d) : "l"(a), "l"(b));
}
__device__ __forceinline__ void fadd2(u64& d, u64 a) {
    asm("add.rn.f32x2 %0, %0, %1;" : "+l"(d) : "l"(a));
}

__global__ void __launch_bounds__(192, 3)
conv_bn_gelu_vpack(const float* __restrict__ x,
                   const float* __restrict__ lw,
                   const float* __restrict__ gamma,
                   const float* __restrict__ beta,
                   float* __restrict__ out)
{
    extern __shared__ __align__(16) char smem_raw[];
    u64*   vp  = (u64*)smem_raw;                  // [ci][vrow(3)][k(28)]  k = col+2
    float* wsm = (float*)(smem_raw + VP_BYTES);   // [ci][och(8)][12]

    // CTA: 2 batch x 2 group x 8 och-tiles(8 och) x 12 row-tiles(2 rows)
    const int cta = blockIdx.x;
    const int rt  = cta % 12;
    const int ot  = (cta / 12) & 7;
    const int g   = (cta / 96) & 1;
    const int b   = cta / 192;
    const int tid = threadIdx.x;
    const int r0  = rt * 2;

    // ---- stage input as vertical pairs: task = (ci, vrow), 192 tasks ----
    {
        const int ci   = tid / 3;
        const int vrow = tid - ci * 3;
        const int rT   = r0 - 1 + vrow;      // top row of pair
        const int rB   = rT + 1;
        const float* xp = x + b * (DIMC * NPIX) + (g * 64 + ci) * NPIX;

        float A[24], Bv[24];
        if ((unsigned)rT < 24u) {
            const float4* s4 = (const float4*)(xp + rT * NPD);
            #pragma unroll
            for (int q = 0; q < 6; q++) {
                float4 v = s4[q];
                A[4*q] = v.x; A[4*q+1] = v.y; A[4*q+2] = v.z; A[4*q+3] = v.w;
            }
        } else {
            #pragma unroll
            for (int c = 0; c < 24; c++) A[c] = 0.0f;
        }
        if ((unsigned)rB < 24u) {
            const float4* s4 = (const float4*)(xp + rB * NPD);
            #pragma unroll
            for (int q = 0; q < 6; q++) {
                float4 v = s4[q];
                Bv[4*q] = v.x; Bv[4*q+1] = v.y; Bv[4*q+2] = v.z; Bv[4*q+3] = v.w;
            }
        } else {
            #pragma unroll
            for (int c = 0; c < 24; c++) Bv[c] = 0.0f;
        }

        // write 28 pairs (k = 0..27, col = k-2; cols <0 or >23 are zero)
        float4* dst = (float4*)(vp + ci * VP_CI + vrow * 28);
        // m = 0: cols -2, -1 -> zeros
        dst[0] = make_float4(0.f, 0.f, 0.f, 0.f);
        #pragma unroll
        for (int m = 1; m < 13; m++) {
            int c0 = 2 * m - 2;
            dst[m] = make_float4(A[c0], Bv[c0], A[c0 + 1], Bv[c0 + 1]);
        }
        // m = 13: cols 24, 25 -> zeros
        dst[13] = make_float4(0.f, 0.f, 0.f, 0.f);
    }

    // ---- stage weights: [ci][och][12 floats] (9 taps + pad) ----
    {
        const float* wb = lw + (g * 64 + ot * 8) * 576;
        #pragma unroll
        for (int it = 0; it < 3; it++) {
            int e = tid + it * 192;
            if (e < 512) {
                int o8 = e & 7, ci = e >> 3;
                const float* src = wb + o8 * 576 + ci * 9;
                float* dst = wsm + ci * W_CI + o8 * 12;
                float w0 = src[0], w1 = src[1], w2 = src[2], w3 = src[3];
                float w4 = src[4], w5 = src[5], w6 = src[6], w7 = src[7];
                float w8 = src[8];
                *(float4*)dst       = make_float4(w0, w1, w2, w3);
                *(float4*)(dst + 4) = make_float4(w4, w5, w6, w7);
                dst[8] = w8;
            }
        }
    }

    // ---- roles: och(8) x cg(3, 8 cols each) x split(8, 8 ci each) ----
    const int och   = tid & 7;
    const int qq    = tid >> 3;      // 0..23
    const int cg    = qq % 3;
    const int split = qq / 3;        // 0..7

    const int   ochg = g * 64 + ot * 8 + och;
    const float sc   = gamma[ochg] * rsqrtf(1.0f + 1e-5f);
    const float bb   = beta[ochg];

    __syncthreads();

    const u64*   vbase = vp + (split * 8) * VP_CI + cg * 8;   // k0 = col0
    const float* wbase = wsm + (split * 8) * W_CI + och * 12;

    u64 acc[8];
    #pragma unroll
    for (int j = 0; j < 8; j++) acc[j] = 0ull;

    #pragma unroll 2
    for (int i = 0; i < 8; i++) {
        const u64*   vc = vbase + i * VP_CI;
        const float* wc = wbase + i * W_CI;

        float4 wA = *(const float4*)wc;
        float4 wB = *(const float4*)(wc + 4);
        float  w8 = wc[8];
        u64 W[9];
        W[0] = pk(wA.x, wA.x); W[1] = pk(wA.y, wA.y); W[2] = pk(wA.z, wA.z);
        W[3] = pk(wA.w, wA.w); W[4] = pk(wB.x, wB.x); W[5] = pk(wB.y, wB.y);
        W[6] = pk(wB.z, wB.z); W[7] = pk(wB.w, wB.w); W[8] = pk(w8, w8);

        #pragma unroll
        for (int di = 0; di < 3; di++) {
            const ulonglong2* pv = (const ulonglong2*)(vc + di * 28);
            u64 P[12];
            #pragma unroll
            for (int m = 0; m < 6; m++) {
                ulonglong2 t = pv[m];
                P[2*m] = t.x; P[2*m + 1] = t.y;
            }
            // P[m] = vertical pair at col = col0 - 2 + m; acc[j] is col0+j
            #pragma unroll
            for (int j = 0; j < 8; j++) {
                ffma2(acc[j], P[j + 1], W[di * 3 + 0]);
                ffma2(acc[j], P[j + 2], W[di * 3 + 1]);
                ffma2(acc[j], P[j + 3], W[di * 3 + 2]);
            }
        }
    }

    // ---- all-to-all split-K reduction in smem (reuse weight region) ----
    __syncthreads();   // weights no longer needed
    u64* red = (u64*)wsm;
    const int gidx = och * 3 + cg;   // 0..23
    {
        ulonglong2* w2 = (ulonglong2*)(red + gidx * 64 + split * 8);
        #pragma unroll
        for (int m = 0; m < 4; m++) {
            ulonglong2 t; t.x = acc[2*m]; t.y = acc[2*m + 1];
            w2[m] = t;
        }
    }
    __syncthreads();

    // thread takes column j = split of its (och, cg) group
    u64 tot = red[gidx * 64 + 0 * 8 + split];
    #pragma unroll
    for (int s = 1; s < 8; s++) fadd2(tot, red[gidx * 64 + s * 8 + split]);

    float vt, vb2;
    upk(vt, vb2, tot);
    float zt = vt  * sc + bb;
    float zb = vb2 * sc + bb;

    const float kI = 0.70710678118654752440f;
    float ot0 = 1.0f + 0.5f * zt * (1.0f + erff(zt * kI));
    float ob0 = 1.0f + 0.5f * zb * (1.0f + erff(zb * kI));

    const int c = cg * 8 + split;
    float* op = out + (b * DIMC + ochg) * NPIX + r0 * NPD + c;
    op[0]   = ot0;
    op[NPD] = ob0;
}

extern "C" void kernel_launch(void* const* d_in, const int* in_sizes, int n_in,
                              void* d_out, int out_size) {
    const float* x     = (const float*)d_in[0];   // (2, 576, 128) flat
    const float* lw    = (const float*)d_in[9];   // local_w (128, 64, 3, 3)
    const float* bnc1g = (const float*)d_in[10];  // bnc1_gamma (128)
    const float* bnc1b = (const float*)d_in[11];  // bnc1_beta (128)
    float* out = (float*)d_out;

    cudaFuncSetAttribute(conv_bn_gelu_vpack,
                         cudaFuncAttributeMaxDynamicSharedMemorySize,
                         SMEM_BYTES);
    conv_bn_gelu_vpack<<<384, 192, SMEM_BYTES>>>(x, lw, bnc1g, bnc1b, out);
}

// round 6
// speedup vs baseline: 1.7171x; 1.7171x over previous
#include <cuda_runtime.h>

// ============================================================================
// MH2SD: attention branch is algebraically dead (softmax over size-1 axis = 1;
// attn rows sum to 1), so out = 1 + gelu(bn(grouped 3x3 conv(x4, local_w))).
//
// R5: coalesced staging (shfl-packed vertical pairs; linear weight copy),
// 2-och x 8-col x 2-row f32x2 thread tile, 16-way split-K, padded reduction.
// ============================================================================

#define NPD   24
#define NPIX  576
#define DIMC  128

#define VP_CI        86                    // u64 per ci (3 vrows * 28 used, +2 pad)
#define W_CI         100                   // floats per ci (8 och * 12, +4 pad)
#define W_OFF_BYTES  44032                 // 64 * 86 * 8
#define RED_STRIDE   17                    // u64 stride per output (16 partials + pad)
#define W_REGION     26112                 // max(64*100*4, 192*17*8)
#define SMEM_BYTES   (W_OFF_BYTES + W_REGION)   // 70144

typedef unsigned long long u64;

__device__ __forceinline__ u64 pk(float lo, float hi) {
    u64 r; asm("mov.b64 %0, {%1, %2};" : "=l"(r) : "f"(lo), "f"(hi)); return r;
}
__device__ __forceinline__ void upk(float& lo, float& hi, u64 v) {
    asm("mov.b64 {%0, %1}, %2;" : "=f"(lo), "=f"(hi) : "l"(v));
}
__device__ __forceinline__ void ffma2(u64& d, u64 a, u64 b) {
    asm("fma.rn.f32x2 %0, %1, %2, %0;" : "+l"(d) : "l"(a), "l"(b));
}
__device__ __forceinline__ void fadd2(u64& d, u64 a) {
    asm("add.rn.f32x2 %0, %0, %1;" : "+l"(d) : "l"(a));
}

__global__ void __launch_bounds__(192, 3)
conv_bn_gelu_r5(const float* __restrict__ x,
                const float* __restrict__ lw,
                const float* __restrict__ gamma,
                const float* __restrict__ beta,
                float* __restrict__ out)
{
    extern __shared__ __align__(16) char smem_raw[];
    u64*   vp  = (u64*)smem_raw;                    // [ci][vrow3][k28] vertical pairs
    float* wsm = (float*)(smem_raw + W_OFF_BYTES);  // [ci][och8][12]
    u64*   red = (u64*)(smem_raw + W_OFF_BYTES);    // reused after main loop

    // CTA: 2 batch x 2 group x 8 och-tiles(8 och) x 12 row-tiles(2 rows)
    const int cta = blockIdx.x;
    const int rt  = cta % 12;
    const int ot  = (cta / 12) & 7;
    const int g   = (cta / 96) & 1;
    const int b   = cta / 192;
    const int tid = threadIdx.x;
    const int r0  = rt * 2;

    // ---- halo zeros: k in {0,1} and {26,27} for every (ci, vrow) ----
    {
        int ci = tid / 3, vr = tid - ci * 3;     // 192 tasks exactly
        u64* hz = vp + ci * VP_CI + vr * 28;
        ulonglong2 z; z.x = 0ull; z.y = 0ull;
        ((ulonglong2*)hz)[0]        = z;
        ((ulonglong2*)(hz + 26))[0] = z;
    }

    // ---- input staging: coalesced LDG + shfl vertical pairing ----
    // task T = (ci, m, rr), rr fastest: warp covers contiguous 4-row blocks.
    {
        const float4* x4 = (const float4*)x + b * 18432 + g * 9216;
        #pragma unroll
        for (int q = 0; q < 8; q++) {
            int T   = tid + 192 * q;             // 0..1535
            int ci  = T / 24;
            int rem = T - ci * 24;
            int m   = rem >> 2;                  // 0..5 (float4 within row)
            int rr  = rem & 3;                   // 0..3 (row in window)
            int gr  = r0 - 1 + rr;
            float4 F = make_float4(0.f, 0.f, 0.f, 0.f);
            if ((unsigned)gr < 24u) F = x4[ci * 144 + gr * 6 + m];
            float gx = __shfl_down_sync(0xffffffffu, F.x, 1);
            float gy = __shfl_down_sync(0xffffffffu, F.y, 1);
            float gz = __shfl_down_sync(0xffffffffu, F.z, 1);
            float gw = __shfl_down_sync(0xffffffffu, F.w, 1);
            if (rr < 3) {
                u64* dst = vp + ci * VP_CI + rr * 28 + (m * 4 + 2);
                ulonglong2 t0, t1;
                t0.x = pk(F.x, gx); t0.y = pk(F.y, gy);
                t1.x = pk(F.z, gz); t1.y = pk(F.w, gw);
                ((ulonglong2*)dst)[0]       = t0;
                ((ulonglong2*)(dst + 2))[0] = t1;
            }
        }
    }

    // ---- weight staging: linear coalesced copy of contiguous 4608-float blk ----
    {
        const float4* w4 = (const float4*)(lw + (g * 64 + ot * 8) * 576);
        #pragma unroll
        for (int q = 0; q < 6; q++) {
            int i4 = tid + 192 * q;              // 0..1151
            float4 v = w4[i4];
            int i   = i4 * 4;
            int och = i / 576;
            int r   = i - och * 576;
            int ci  = r / 9;
            int tap = r - ci * 9;
            float vals[4] = {v.x, v.y, v.z, v.w};
            float* base = wsm + och * 12;
            #pragma unroll
            for (int e = 0; e < 4; e++) {
                base[ci * W_CI + tap] = vals[e];
                tap++;
                if (tap == 9) { tap = 0; ci++; }
            }
        }
    }

    __syncthreads();

    // ---- roles: op(4 och-pairs) x cg(3 col-groups of 8) x split(16, 4 ci) ----
    const int op    = tid & 3;
    const int cg    = (tid >> 2) % 3;
    const int split = tid / 12;                  // 0..15

    u64 acc[16];
    #pragma unroll
    for (int j = 0; j < 16; j++) acc[j] = 0ull;

    const u64*   vbase = vp  + (split * 4) * VP_CI + cg * 8;
    const float* wbase = wsm + (split * 4) * W_CI + (op * 2) * 12;

    #pragma unroll
    for (int i = 0; i < 4; i++) {
        const u64*   vc = vbase + i * VP_CI;
        const float* wc = wbase + i * W_CI;
        #pragma unroll
        for (int di = 0; di < 3; di++) {
            const ulonglong2* pv = (const ulonglong2*)(vc + di * 28);
            u64 P[12];
            #pragma unroll
            for (int mm = 0; mm < 6; mm++) {
                ulonglong2 t = pv[mm];
                P[2 * mm] = t.x; P[2 * mm + 1] = t.y;
            }
            float a0 = wc[di * 3 + 0], a1 = wc[di * 3 + 1], a2 = wc[di * 3 + 2];
            float b0 = wc[12 + di * 3 + 0], b1 = wc[12 + di * 3 + 1], b2 = wc[12 + di * 3 + 2];
            u64 WA0 = pk(a0, a0), WA1 = pk(a1, a1), WA2 = pk(a2, a2);
            u64 WB0 = pk(b0, b0), WB1 = pk(b1, b1), WB2 = pk(b2, b2);
            #pragma unroll
            for (int j = 0; j < 8; j++) {
                ffma2(acc[j],     P[j + 1], WA0);
                ffma2(acc[j],     P[j + 2], WA1);
                ffma2(acc[j],     P[j + 3], WA2);
                ffma2(acc[8 + j], P[j + 1], WB0);
                ffma2(acc[8 + j], P[j + 2], WB1);
                ffma2(acc[8 + j], P[j + 3], WB2);
            }
        }
    }

    // ---- split-K reduction (reuse weight region; padded stride 17) ----
    __syncthreads();   // everyone done reading wsm
    #pragma unroll
    for (int oo = 0; oo < 2; oo++) {
        #pragma unroll
        for (int j = 0; j < 8; j++) {
            int oidx = (op * 2 + oo) * 24 + cg * 8 + j;
            red[oidx * RED_STRIDE + split] = acc[oo * 8 + j];
        }
    }
    __syncthreads();

    // ---- epilogue: 1 thread per (och, col) vertical pair ----
    {
        const int och8 = tid / 24;
        const int col  = tid - och8 * 24;
        const u64* rb  = red + tid * RED_STRIDE;
        u64 tot = rb[0];
        #pragma unroll
        for (int s = 1; s < 16; s++) fadd2(tot, rb[s]);

        const int   ochg = g * 64 + ot * 8 + och8;
        const float sc   = gamma[ochg] * rsqrtf(1.0f + 1e-5f);
        const float bb   = beta[ochg];

        float vt, vb;
        upk(vt, vb, tot);
        float zt = vt * sc + bb;
        float zb = vb * sc + bb;

        const float kI = 0.70710678118654752440f;
        float otv = 1.0f + 0.5f * zt * (1.0f + erff(zt * kI));
        float obv = 1.0f + 0.5f * zb * (1.0f + erff(zb * kI));

        float* opt = out + (b * DIMC + ochg) * NPIX + r0 * NPD + col;
        opt[0]   = otv;
        opt[NPD] = obv;
    }
}

extern "C" void kernel_launch(void* const* d_in, const int* in_sizes, int n_in,
                              void* d_out, int out_size) {
    const float* x     = (const float*)d_in[0];   // (2, 576, 128) flat
    const float* lw    = (const float*)d_in[9];   // local_w (128, 64, 3, 3)
    const float* bnc1g = (const float*)d_in[10];  // bnc1_gamma (128)
    const float* bnc1b = (const float*)d_in[11];  // bnc1_beta (128)
    float* out = (float*)d_out;

    cudaFuncSetAttribute(conv_bn_gelu_r5,
                         cudaFuncAttributeMaxDynamicSharedMemorySize,
                         SMEM_BYTES);
    conv_bn_gelu_r5<<<384, 192, SMEM_BYTES>>>(x, lw, bnc1g, bnc1b, out);
}